// round 5
// baseline (speedup 1.0000x reference)
#include <cuda_runtime.h>
#include <cuda_fp16.h>

#define DIM       33
#define BINS      32
#define NTHREADS  1024
#define NGROUPS   49
#define PLANE4    1048576         // 2048*2048/4 float4s per plane
#define TOTAL4    4194304         // 4 batches * PLANE4 float4s per channel
#define NSUPER    32768           // TOTAL4 / (32 lanes * 4 iters)
#define NWARPS_CH 1568            // 49 CTAs * 32 warps per channel
#define NPAIR     (DIM*DIM*BINS)  // 34848 half2 pairs per channel
#define SMEM_BYTES (NPAIR * 4)    // 139392 B

// Per-channel work-stealing counters (each on its own 128B L2 line).
__device__ unsigned int g_ctr[96];

__global__ void init_ctr_kernel() {
    if (threadIdx.x < 96) g_ctr[threadIdx.x] = 0;
    __syncthreads();
    if (threadIdx.x < 3) g_ctr[threadIdx.x * 32] = NWARPS_CH;
}

// Persistent channel-split trilinear LUT kernel with warp-level work stealing.
// CTA b: channel = b%3. fp16 overlapping-pair smem LUT:
// P[(b0*33+g0)*32 + r0] = (L[r0], L[r0+1]) -> each corner pair is ONE LDS.32.
// Warps steal super-units (4 iters x 32 float4s) from a per-channel atomic
// queue to eliminate end-of-kernel straggler spread.
__global__ __launch_bounds__(NTHREADS, 1)
void lut3d_kernel(const float* __restrict__ x, const float* __restrict__ lut,
                  float* __restrict__ out) {
    extern __shared__ __half2 sP[];
    const int ch   = blockIdx.x % 3;
    const int grp  = blockIdx.x / 3;
    const int wid  = threadIdx.x >> 5;
    const int lane = threadIdx.x & 31;

    // Build smem pair table for this channel (coalesced reads of 139KB slab).
    const float* lc = lut + ch * (DIM * DIM * DIM);
    for (int i = threadIdx.x; i < NPAIR; i += NTHREADS) {
        int r0 = i & (BINS - 1);
        int j  = i >> 5;            // combined (b0*33 + g0)
        float v0 = lc[j * DIM + r0];
        float v1 = lc[j * DIM + r0 + 1];
        sP[i] = __floats2half2_rn(v0, v1);
    }
    __syncthreads();

    const float4* __restrict__ X = reinterpret_cast<const float4*>(x);
    float4* __restrict__ O       = reinterpret_cast<float4*>(out);
    unsigned int* ctr = &g_ctr[ch * 32];

    // First super-unit is static (warp's global id); later ones are stolen.
    int su = grp * 32 + wid;
    int it = 0;

    // float4 position for (su, it): p = (su*4 + it)*32 + lane
    int p    = (su * 4 + it) * 32 + lane;
    int base = (p >> 20) * 3 * PLANE4 + (p & (PLANE4 - 1));
    float4 R  = X[base];
    float4 G  = X[base + PLANE4];
    float4 Bv = X[base + 2 * PLANE4];

    while (true) {
        // Next work item: advance iter, or steal a new super-unit every 4 iters.
        int it_n = it + 1;
        int su_n = su;
        if (it_n == 4) {
            it_n = 0;
            unsigned int g = 0;
            if (lane == 0) g = atomicAdd(ctr, 1u);
            su_n = (int)__shfl_sync(0xffffffffu, g, 0);
        }
        bool more = (su_n < NSUPER);
        int basen = 0;
        float4 Rn, Gn, Bn;
        if (more) {
            int pn = (su_n * 4 + it_n) * 32 + lane;
            basen  = (pn >> 20) * 3 * PLANE4 + (pn & (PLANE4 - 1));
            Rn = X[basen];
            Gn = X[basen + PLANE4];
            Bn = X[basen + 2 * PLANE4];
        }

        float rp[4] = {R.x, R.y, R.z, R.w};
        float gp[4] = {G.x, G.y, G.z, G.w};
        float bp[4] = {Bv.x, Bv.y, Bv.z, Bv.w};
        float o[4];
        #pragma unroll
        for (int k = 0; k < 4; k++) {
            float rr = rp[k] * (float)BINS;
            float gg = gp[k] * (float)BINS;
            float bb = bp[k] * (float)BINS;
            // x in [0,1) => floor <= 31; no clamp needed.
            int r0 = __float2int_rd(rr);
            int g0 = __float2int_rd(gg);
            int b0 = __float2int_rd(bb);
            float fr = rr - (float)r0;
            float fg = gg - (float)g0;
            float fb = bb - (float)b0;
            int idx = (b0 * DIM + g0) * BINS + r0;
            // 4 corner pairs = 4 aligned LDS.32 (immediate offsets)
            float2 v00 = __half22float2(sP[idx]);
            float2 v01 = __half22float2(sP[idx + BINS]);            // g0+1
            float2 v10 = __half22float2(sP[idx + DIM * BINS]);      // b0+1
            float2 v11 = __half22float2(sP[idx + DIM * BINS + BINS]);
            // factored trilinear: 4 r-lerps, 2 g-lerps, 1 b-lerp
            float c00 = fmaf(fr, v00.y - v00.x, v00.x);
            float c01 = fmaf(fr, v01.y - v01.x, v01.x);
            float c10 = fmaf(fr, v10.y - v10.x, v10.x);
            float c11 = fmaf(fr, v11.y - v11.x, v11.x);
            float c0  = fmaf(fg, c01 - c00, c00);
            float c1  = fmaf(fg, c11 - c10, c10);
            o[k] = fmaf(fb, c1 - c0, c0);
        }
        O[base + ch * PLANE4] = make_float4(o[0], o[1], o[2], o[3]);

        if (!more) break;
        su = su_n; it = it_n; base = basen; R = Rn; G = Gn; Bv = Bn;
    }
}

extern "C" void kernel_launch(void* const* d_in, const int* in_sizes, int n_in,
                              void* d_out, int out_size) {
    const float* x   = (const float*)d_in[0];
    const float* lut = (const float*)d_in[1];
    // x has 50,331,648 elems; LUT has 107,811. Swap defensively if order differs.
    if (n_in >= 2 && in_sizes[0] < in_sizes[1]) {
        x   = (const float*)d_in[1];
        lut = (const float*)d_in[0];
    }
    init_ctr_kernel<<<1, 96>>>();
    cudaFuncSetAttribute((const void*)lut3d_kernel,
                         cudaFuncAttributeMaxDynamicSharedMemorySize, SMEM_BYTES);
    lut3d_kernel<<<3 * NGROUPS, NTHREADS, SMEM_BYTES>>>(x, lut, (float*)d_out);
}

// round 7
// speedup vs baseline: 1.0030x; 1.0030x over previous
#include <cuda_runtime.h>
#include <cuda_fp16.h>

#define DIM       33
#define BINS      32
#define NTHREADS  1024
#define NGROUPS   49
#define PLANE4    1048576         // 2048*2048/4 float4s per plane
#define TOTAL4    4194304         // 4 batches * PLANE4 float4s per channel
#define ITERS     8               // loop-iters per super-unit
#define NSUPER    16384           // TOTAL4 / (32 lanes * ITERS)
#define NWARPS_CH 1568            // 49 CTAs * 32 warps per channel
#define NPAIR     (DIM*DIM*BINS)  // 34848 half2 pairs per channel
#define SMEM_BYTES (NPAIR * 4)    // 139392 B

// Per-channel work-stealing counters (each on its own 128B L2 line).
__device__ unsigned int g_ctr[96];

__global__ void init_ctr_kernel() {
    if (threadIdx.x < 96) g_ctr[threadIdx.x] = 0;
    __syncthreads();
    if (threadIdx.x < 3) g_ctr[threadIdx.x * 32] = NWARPS_CH;
}

// Persistent channel-split trilinear LUT kernel with DECOUPLED work stealing:
// the next super-unit is stolen when a warp *enters* the current one, and only
// consumed ITERS-1 iterations later, so the ~318-cycle global atomic is fully
// hidden behind useful work (R5's mistake was stealing in the prefetch path).
// fp16 overlapping-pair smem LUT: P[(b0*33+g0)*32 + r0] = (L[r0], L[r0+1]);
// each trilinear corner pair is ONE aligned LDS.32 (4 per pixel).
__global__ __launch_bounds__(NTHREADS, 1)
void lut3d_kernel(const float* __restrict__ x, const float* __restrict__ lut,
                  float* __restrict__ out) {
    extern __shared__ __half2 sP[];
    const int ch   = blockIdx.x % 3;
    const int grp  = blockIdx.x / 3;
    const int wid  = threadIdx.x >> 5;
    const int lane = threadIdx.x & 31;

    // Build smem pair table for this channel (coalesced reads of 139KB slab).
    const float* lc = lut + ch * (DIM * DIM * DIM);
    for (int i = threadIdx.x; i < NPAIR; i += NTHREADS) {
        int r0 = i & (BINS - 1);
        int j  = i >> 5;            // combined (b0*33 + g0)
        float v0 = lc[j * DIM + r0];
        float v1 = lc[j * DIM + r0 + 1];
        sP[i] = __floats2half2_rn(v0, v1);
    }
    __syncthreads();

    const float4* __restrict__ X = reinterpret_cast<const float4*>(x);
    float4* __restrict__ O       = reinterpret_cast<float4*>(out);
    unsigned int* ctr = &g_ctr[ch * 32];

    // Initial super-unit is static (global warp id); steal the NEXT one now —
    // it won't be consumed for another ITERS-1 iterations.
    int su = grp * 32 + wid;
    int it = 0;
    int su_next;
    {
        unsigned int g = 0;
        if (lane == 0) g = atomicAdd(ctr, 1u);
        su_next = (int)__shfl_sync(0xffffffffu, g, 0);
    }

    // float4 position for (su, it): p = (su*ITERS + it)*32 + lane
    int p    = (su * ITERS + it) * 32 + lane;
    int base = (p >> 20) * 3 * PLANE4 + (p & (PLANE4 - 1));
    float4 R  = X[base];
    float4 G  = X[base + PLANE4];
    float4 Bv = X[base + 2 * PLANE4];

    while (true) {
        // Next work item (su_next was resolved ~ITERS iterations ago).
        int it_n = it + 1;
        int su_n = su;
        bool roll = (it_n == ITERS);
        if (roll) { it_n = 0; su_n = su_next; }
        bool more = !roll || (su_n < NSUPER);

        int basen = 0;
        float4 Rn, Gn, Bn;
        if (more) {
            int pn = (su_n * ITERS + it_n) * 32 + lane;
            basen  = (pn >> 20) * 3 * PLANE4 + (pn & (PLANE4 - 1));
            Rn = X[basen];
            Gn = X[basen + PLANE4];
            Bn = X[basen + 2 * PLANE4];
        }

        float rp[4] = {R.x, R.y, R.z, R.w};
        float gp[4] = {G.x, G.y, G.z, G.w};
        float bp[4] = {Bv.x, Bv.y, Bv.z, Bv.w};
        float o[4];
        #pragma unroll
        for (int k = 0; k < 4; k++) {
            float rr = rp[k] * (float)BINS;
            float gg = gp[k] * (float)BINS;
            float bb = bp[k] * (float)BINS;
            // x in [0,1) => floor <= 31; no clamp needed.
            int r0 = __float2int_rd(rr);
            int g0 = __float2int_rd(gg);
            int b0 = __float2int_rd(bb);
            float fr = rr - (float)r0;
            float fg = gg - (float)g0;
            float fb = bb - (float)b0;
            int idx = (b0 * DIM + g0) * BINS + r0;
            // 4 corner pairs = 4 aligned LDS.32 (immediate offsets)
            float2 v00 = __half22float2(sP[idx]);
            float2 v01 = __half22float2(sP[idx + BINS]);            // g0+1
            float2 v10 = __half22float2(sP[idx + DIM * BINS]);      // b0+1
            float2 v11 = __half22float2(sP[idx + DIM * BINS + BINS]);
            // factored trilinear: 4 r-lerps, 2 g-lerps, 1 b-lerp
            float c00 = fmaf(fr, v00.y - v00.x, v00.x);
            float c01 = fmaf(fr, v01.y - v01.x, v01.x);
            float c10 = fmaf(fr, v10.y - v10.x, v10.x);
            float c11 = fmaf(fr, v11.y - v11.x, v11.x);
            float c0  = fmaf(fg, c01 - c00, c00);
            float c1  = fmaf(fg, c11 - c10, c10);
            o[k] = fmaf(fb, c1 - c0, c0);
        }
        O[base + ch * PLANE4] = make_float4(o[0], o[1], o[2], o[3]);

        if (!more) break;
        su = su_n; it = it_n; base = basen; R = Rn; G = Gn; Bv = Bn;
        if (roll) {
            // Entering a fresh super-unit: steal the one after it, off the
            // critical path (consumed ITERS-1 iterations from now).
            unsigned int g = 0;
            if (lane == 0) g = atomicAdd(ctr, 1u);
            su_next = (int)__shfl_sync(0xffffffffu, g, 0);
        }
    }
}

extern "C" void kernel_launch(void* const* d_in, const int* in_sizes, int n_in,
                              void* d_out, int out_size) {
    const float* x   = (const float*)d_in[0];
    const float* lut = (const float*)d_in[1];
    // x has 50,331,648 elems; LUT has 107,811. Swap defensively if order differs.
    if (n_in >= 2 && in_sizes[0] < in_sizes[1]) {
        x   = (const float*)d_in[1];
        lut = (const float*)d_in[0];
    }
    init_ctr_kernel<<<1, 96>>>();
    cudaFuncSetAttribute((const void*)lut3d_kernel,
                         cudaFuncAttributeMaxDynamicSharedMemorySize, SMEM_BYTES);
    lut3d_kernel<<<3 * NGROUPS, NTHREADS, SMEM_BYTES>>>(x, lut, (float*)d_out);
}